// round 1
// baseline (speedup 1.0000x reference)
#include <cuda_runtime.h>
#include <cuda_bf16.h>
#include <math.h>

// Problem constants
#define SEQ 1536
#define BATCH 2
#define DMODEL 768
#define NHEAD 24
#define DHEAD 32
#define FFDIM 3072
#define NTOK (SEQ * BATCH)          // 3072 tokens, token t = s*B + b
#define QKVDIM (3 * DMODEL)         // 2304
#define ATTN_SCALE 0.17677669529663688f  // 1/sqrt(32)

// ---------------- scratch (device globals; no allocs allowed) ----------------
__device__ float g_x[NTOK * DMODEL];      // residual stream (S,B,D)
__device__ float g_h[NTOK * DMODEL];      // LN output
__device__ float g_qkv[NTOK * QKVDIM];    // qkv projection
__device__ float g_ctx[NTOK * DMODEL];    // attention context
__device__ float g_m[NTOK * FFDIM];       // gelu(fc) output

// ---------------- embedding ----------------
__global__ void embed_kernel(const int* __restrict__ ids, const int* __restrict__ pos,
                             const float* __restrict__ wte, const float* __restrict__ wpe,
                             float* __restrict__ x) {
    int t = blockIdx.x;               // t = s*B + b
    int s = t / BATCH, b = t % BATCH;
    int id = ids[b * SEQ + s];
    int p  = pos[b * SEQ + s];
    const float* te = wte + (size_t)id * DMODEL;
    const float* pe = wpe + (size_t)p * DMODEL;
    for (int d = threadIdx.x; d < DMODEL; d += blockDim.x)
        x[(size_t)t * DMODEL + d] = te[d] + pe[d];
}

// ---------------- layernorm (row of 768, one block per token) ----------------
__global__ void ln_kernel(const float* __restrict__ in, const float* __restrict__ w,
                          const float* __restrict__ b, float* __restrict__ out) {
    int t = blockIdx.x;
    const float* row = in + (size_t)t * DMODEL;
    float s = 0.f, ss = 0.f;
    for (int d = threadIdx.x; d < DMODEL; d += 256) {
        float v = row[d];
        s += v;
        ss = fmaf(v, v, ss);
    }
    __shared__ float red0[8], red1[8];
    __shared__ float s_mu, s_inv;
    int lane = threadIdx.x & 31, wid = threadIdx.x >> 5;
#pragma unroll
    for (int o = 16; o; o >>= 1) {
        s  += __shfl_xor_sync(0xffffffffu, s, o);
        ss += __shfl_xor_sync(0xffffffffu, ss, o);
    }
    if (lane == 0) { red0[wid] = s; red1[wid] = ss; }
    __syncthreads();
    if (threadIdx.x == 0) {
        float a = 0.f, c = 0.f;
#pragma unroll
        for (int i = 0; i < 8; i++) { a += red0[i]; c += red1[i]; }
        float mu = a * (1.0f / DMODEL);
        float var = c * (1.0f / DMODEL) - mu * mu;
        s_mu = mu;
        s_inv = rsqrtf(var + 1e-5f);
    }
    __syncthreads();
    float mu = s_mu, inv = s_inv;
    for (int d = threadIdx.x; d < DMODEL; d += 256)
        out[(size_t)t * DMODEL + d] = (row[d] - mu) * inv * w[d] + b[d];
}

// ---------------- tiled SGEMM: C[m][n] = sum_k A[m][k]*W[n][k] (+bias,+epi) ----------------
// A: (M,K) row-major, W: (N,K) row-major. Tile 64x64, K-step 16, 256 threads, 4x4/thread.
// All M,N,K here are multiples of 64/64/16 -> no bounds checks.
// EPI: 0 = bias only; 1 = bias + residual add (res same shape as C); 2 = bias + exact GELU
template <int EPI>
__global__ void gemm_nt(const float* __restrict__ A, const float* __restrict__ W,
                        const float* __restrict__ bias, const float* __restrict__ res,
                        float* __restrict__ C, int M, int N, int K) {
    __shared__ float As[16][68];
    __shared__ float Bs[16][68];
    int tid = threadIdx.x;
    int tx = tid & 15, ty = tid >> 4;
    int m0 = blockIdx.y * 64, n0 = blockIdx.x * 64;
    const float* Ab = A + (size_t)m0 * K;
    const float* Wb = W + (size_t)n0 * K;

    float acc[4][4];
#pragma unroll
    for (int i = 0; i < 4; i++)
#pragma unroll
        for (int j = 0; j < 4; j++) acc[i][j] = 0.f;

    for (int k0 = 0; k0 < K; k0 += 16) {
#pragma unroll
        for (int e = 0; e < 4; e++) {
            int idx = tid + e * 256;
            int r = idx >> 4, c = idx & 15;
            As[c][r] = Ab[(size_t)r * K + k0 + c];
            Bs[c][r] = Wb[(size_t)r * K + k0 + c];
        }
        __syncthreads();
#pragma unroll
        for (int kk = 0; kk < 16; kk++) {
            float4 a4 = *(const float4*)&As[kk][ty * 4];
            float4 b4 = *(const float4*)&Bs[kk][tx * 4];
            float av[4] = {a4.x, a4.y, a4.z, a4.w};
            float bw[4] = {b4.x, b4.y, b4.z, b4.w};
#pragma unroll
            for (int i = 0; i < 4; i++)
#pragma unroll
                for (int j = 0; j < 4; j++)
                    acc[i][j] = fmaf(av[i], bw[j], acc[i][j]);
        }
        __syncthreads();
    }

#pragma unroll
    for (int i = 0; i < 4; i++) {
        int m = m0 + ty * 4 + i;
#pragma unroll
        for (int j = 0; j < 4; j++) {
            int n = n0 + tx * 4 + j;
            float v = acc[i][j] + bias[n];
            if (EPI == 1) v += res[(size_t)m * N + n];
            if (EPI == 2) v = 0.5f * v * (1.0f + erff(v * 0.70710678118654752f));
            C[(size_t)m * N + n] = v;
        }
    }
}

// ---------------- attention: warp-per-query-row online softmax ----------------
// qkv row layout per token: head h occupies cols [h*96, h*96+96): q | k | v (32 each)
__global__ void attn_kernel(const float* __restrict__ qkv, float* __restrict__ ctx) {
    int warp = threadIdx.x >> 5, lane = threadIdx.x & 31;
    int sq = blockIdx.x * 8 + warp;        // query position
    int bh = blockIdx.y;
    int b = bh / NHEAD, h = bh % NHEAD;

    const float* qrow = qkv + ((size_t)sq * BATCH + b) * QKVDIM + h * 96;
    float q = qrow[lane] * ATTN_SCALE;

    float mmax = -1e30f, ssum = 0.f, acc = 0.f;
    for (int kk = 0; kk <= sq; kk++) {
        const float* kvrow = qkv + ((size_t)kk * BATCH + b) * QKVDIM + h * 96;
        float score = q * kvrow[32 + lane];
#pragma unroll
        for (int o = 16; o; o >>= 1) score += __shfl_xor_sync(0xffffffffu, score, o);
        float mnew = fmaxf(mmax, score);
        float corr = __expf(mmax - mnew);
        float p = __expf(score - mnew);
        ssum = ssum * corr + p;
        acc = acc * corr + p * kvrow[64 + lane];
        mmax = mnew;
    }
    ctx[((size_t)sq * BATCH + b) * DMODEL + h * DHEAD + lane] = acc / ssum;
}

// ---------------- launch ----------------
struct LayerW {
    const float *ln1w, *ln1b, *wqkv, *bqkv, *wo, *bo, *ln2w, *ln2b, *wfc, *bfc, *wproj, *bproj;
};

extern "C" void kernel_launch(void* const* d_in, const int* in_sizes, int n_in,
                              void* d_out, int out_size) {
    const int*   ids  = (const int*)d_in[0];
    const int*   pos  = (const int*)d_in[1];
    // d_in[2] = attn_mask (causal, known statically) — unused
    const float* wte  = (const float*)d_in[3];
    const float* wpe  = (const float*)d_in[4];
    LayerW L[2];
    for (int l = 0; l < 2; l++) {
        int o = 5 + l * 12;
        L[l].ln1w  = (const float*)d_in[o + 0];
        L[l].ln1b  = (const float*)d_in[o + 1];
        L[l].wqkv  = (const float*)d_in[o + 2];
        L[l].bqkv  = (const float*)d_in[o + 3];
        L[l].wo    = (const float*)d_in[o + 4];
        L[l].bo    = (const float*)d_in[o + 5];
        L[l].ln2w  = (const float*)d_in[o + 6];
        L[l].ln2b  = (const float*)d_in[o + 7];
        L[l].wfc   = (const float*)d_in[o + 8];
        L[l].bfc   = (const float*)d_in[o + 9];
        L[l].wproj = (const float*)d_in[o + 10];
        L[l].bproj = (const float*)d_in[o + 11];
    }
    const float* lnfw = (const float*)d_in[29];
    const float* lnfb = (const float*)d_in[30];
    float* out = (float*)d_out;

    float* x   = nullptr;  cudaGetSymbolAddress((void**)&x,   g_x);
    float* h   = nullptr;  cudaGetSymbolAddress((void**)&h,   g_h);
    float* qkv = nullptr;  cudaGetSymbolAddress((void**)&qkv, g_qkv);
    float* ctx = nullptr;  cudaGetSymbolAddress((void**)&ctx, g_ctx);
    float* mbuf= nullptr;  cudaGetSymbolAddress((void**)&mbuf,g_m);

    embed_kernel<<<NTOK, 256>>>(ids, pos, wte, wpe, x);

    for (int l = 0; l < 2; l++) {
        // LN1
        ln_kernel<<<NTOK, 256>>>(x, L[l].ln1w, L[l].ln1b, h);
        // qkv = h @ wqkv^T + bqkv : (3072, 2304)
        {
            dim3 g(QKVDIM / 64, NTOK / 64);
            gemm_nt<0><<<g, 256>>>(h, L[l].wqkv, L[l].bqkv, nullptr, qkv, NTOK, QKVDIM, DMODEL);
        }
        // attention -> ctx (3072, 768)
        {
            dim3 g(SEQ / 8, BATCH * NHEAD);
            attn_kernel<<<g, 256>>>(qkv, ctx);
        }
        // x = x + ctx @ wo^T + bo
        {
            dim3 g(DMODEL / 64, NTOK / 64);
            gemm_nt<1><<<g, 256>>>(ctx, L[l].wo, L[l].bo, x, x, NTOK, DMODEL, DMODEL);
        }
        // LN2
        ln_kernel<<<NTOK, 256>>>(x, L[l].ln2w, L[l].ln2b, h);
        // m = gelu(h @ wfc^T + bfc) : (3072, 3072)
        {
            dim3 g(FFDIM / 64, NTOK / 64);
            gemm_nt<2><<<g, 256>>>(h, L[l].wfc, L[l].bfc, nullptr, mbuf, NTOK, FFDIM, DMODEL);
        }
        // x = x + m @ wproj^T + bproj
        {
            dim3 g(DMODEL / 64, NTOK / 64);
            gemm_nt<1><<<g, 256>>>(mbuf, L[l].wproj, L[l].bproj, x, x, NTOK, DMODEL, FFDIM);
        }
    }

    // final LN straight into d_out
    ln_kernel<<<NTOK, 256>>>(x, lnfw, lnfb, out);
    (void)in_sizes; (void)n_in; (void)out_size;
}